// round 7
// baseline (speedup 1.0000x reference)
#include <cuda_runtime.h>
#include <math.h>
#include <stdint.h>

#define CC   128
#define NPTS 4096
#define TN   32
#define NG   16
#define OPT  8
#define OP2  4
#define NTHR 512
#define EPSV 1e-12f

// Pre-expanded (se3) + transposed weights: Wt[c][o] = W[o][c]
__device__ float g_W1t [CC * CC];
__device__ float g_W2t [CC * CC];
__device__ float g_W3t [2 * CC * CC];
__device__ float g_svWt[CC * CC];
__device__ float g_vsdWt[CC * CC];
__device__ float g_vsWt[CC * CC];
__device__ float g_ssWt[CC * CC];

// ---------------------------------------------------------------------------
// Prep: expand se3 weights (append 1 - rowsum column) and transpose everything.
// ---------------------------------------------------------------------------
__global__ void prep_kernel(const float* __restrict__ weight,        // [128,127]
                            const float* __restrict__ sv_W,          // [128,128]
                            const float* __restrict__ cross_weight,  // [128,127]
                            const float* __restrict__ crossfc_weight,// [128,255]
                            const float* __restrict__ vsdir_weight,  // [128,128]
                            const float* __restrict__ vs_W,          // [128,128]
                            const float* __restrict__ ss_W)          // [128,128]
{
    const int o = blockIdx.x;
    const int t = threadIdx.x;
    __shared__ float sred[128];

    float w = (t < CC - 1) ? weight[o * (CC - 1) + t] : 0.f;
    sred[t] = w; __syncthreads();
    for (int k = 64; k > 0; k >>= 1) { if (t < k) sred[t] += sred[t + k]; __syncthreads(); }
    float rs1 = sred[0]; __syncthreads();
    if (t < CC - 1) g_W1t[t * CC + o] = w;
    else            g_W1t[(CC - 1) * CC + o] = 1.f - rs1;

    float w2 = (t < CC - 1) ? cross_weight[o * (CC - 1) + t] : 0.f;
    sred[t] = w2; __syncthreads();
    for (int k = 64; k > 0; k >>= 1) { if (t < k) sred[t] += sred[t + k]; __syncthreads(); }
    float rs2 = sred[0]; __syncthreads();
    if (t < CC - 1) g_W2t[t * CC + o] = w2;
    else            g_W2t[(CC - 1) * CC + o] = 1.f - rs2;

    float a0 = crossfc_weight[o * (2 * CC - 1) + t];
    float a1 = (t < CC - 1) ? crossfc_weight[o * (2 * CC - 1) + CC + t] : 0.f;
    sred[t] = a0 + a1; __syncthreads();
    for (int k = 64; k > 0; k >>= 1) { if (t < k) sred[t] += sred[t + k]; __syncthreads(); }
    float rs3 = sred[0]; __syncthreads();
    g_W3t[t * CC + o] = a0;
    if (t < CC - 1) g_W3t[(CC + t) * CC + o] = a1;
    else            g_W3t[(2 * CC - 1) * CC + o] = 1.f - rs3;

    g_svWt [t * CC + o] = sv_W        [o * CC + t];
    g_vsdWt[t * CC + o] = vsdir_weight[o * CC + t];
    g_vsWt [t * CC + o] = vs_W        [o * CC + t];
    g_ssWt [t * CC + o] = ss_W        [o * CC + t];
}

// ---- packed f32x2 helpers ----
#define FMA2(acc, w, x) \
    asm("fma.rn.f32x2 %0, %1, %2, %3;" : "=l"(acc) : "l"(w), "l"(x), "l"(acc))
#define PACK_DUP(out, x) \
    asm("mov.b64 %0, {%1, %1};" : "=l"(out) : "r"(__float_as_uint(x)))

__device__ __forceinline__ float lo2(unsigned long long v) { return __uint_as_float((unsigned)v); }
__device__ __forceinline__ float hi2(unsigned long long v) { return __uint_as_float((unsigned)(v >> 32)); }
__device__ __forceinline__ unsigned long long pack2(float lo, float hi) {
    return (unsigned long long)__float_as_uint(lo) |
           ((unsigned long long)__float_as_uint(hi) << 32);
}

// Load 8 consecutive transposed-weight floats as 4 packed u64 pairs (2x LDG.128).
__device__ __forceinline__ void load_w4x2(const float* __restrict__ base, unsigned long long* w2)
{
    const ulonglong2* p = (const ulonglong2*)base;
    ulonglong2 a = p[0], b = p[1];
    w2[0] = a.x; w2[1] = a.y; w2[2] = b.x; w2[3] = b.y;
}

// ---------------------------------------------------------------------------
// Fused kernel: one block = one (b, 32-column) tile. 512 threads, 1 block/SM
// (smem padded so a second block can't fit -> ~108KB L1D for weight caching).
//   nl = tid & 31  -> column within tile
//   og = tid >> 5  -> output-channel group (8 channels per thread, 16 groups)
// ---------------------------------------------------------------------------
__global__ void __launch_bounds__(NTHR, 1)
fused_kernel(const float* __restrict__ v_in, const float* __restrict__ s_in,
             const float* __restrict__ sv_b, const float* __restrict__ vs_b,
             const float* __restrict__ ss_b, float* __restrict__ out, int B)
{
    extern __shared__ float sm[];
    float* A   = sm;                     // [384][32]  x_c, later v_cross
    float* Bm  = sm + 3 * CC * TN;       // [384][32]  s+p, later v1
    float* red = sm + 6 * CC * TN;       // [96][32]

    const int tid = threadIdx.x;
    const int nl  = tid & 31;
    const int og  = tid >> 5;            // 0..15
    const int ob  = og * OPT;

    const int b  = blockIdx.x >> 7;
    const int n0 = (blockIdx.x & 127) * TN;

    // ---- load x -> A, s -> Bm[0:128] ----
    {
        const float* src = v_in + ((size_t)b * (3 * CC)) * NPTS + n0 + nl;
        #pragma unroll
        for (int it = 0; it < 24; it++) {
            int r = og + it * NG;
            A[r * TN + nl] = src[(size_t)r * NPTS];
        }
        const float* ssrc = s_in + ((size_t)b * CC) * NPTS + n0 + nl;
        #pragma unroll
        for (int it = 0; it < 8; it++) {
            int r = og + it * NG;
            Bm[r * TN + nl] = ssrc[(size_t)r * NPTS];
        }
    }
    __syncthreads();

    // ---- x channel mean; center A in place ----
    float mx, my, mz;
    {
        float px = 0, py = 0, pz = 0;
        #pragma unroll
        for (int j = 0; j < OPT; j++) {
            int c = ob + j;
            px += A[(3 * c + 0) * TN + nl];
            py += A[(3 * c + 1) * TN + nl];
            pz += A[(3 * c + 2) * TN + nl];
        }
        red[(og * 6 + 0) * TN + nl] = px;
        red[(og * 6 + 1) * TN + nl] = py;
        red[(og * 6 + 2) * TN + nl] = pz;
    }
    __syncthreads();
    mx = 0; my = 0; mz = 0;
    #pragma unroll
    for (int g = 0; g < NG; g++) {
        mx += red[(g * 6 + 0) * TN + nl];
        my += red[(g * 6 + 1) * TN + nl];
        mz += red[(g * 6 + 2) * TN + nl];
    }
    __syncthreads();
    mx *= (1.f / CC); my *= (1.f / CC); mz *= (1.f / CC);
    #pragma unroll
    for (int j = 0; j < OPT; j++) {
        int c = ob + j;
        A[(3 * c + 0) * TN + nl] -= mx;
        A[(3 * c + 1) * TN + nl] -= my;
        A[(3 * c + 2) * TN + nl] -= mz;
    }
    __syncthreads();

    unsigned long long aX[OP2], aY[OP2], aZ[OP2];
    float ux[OPT], uy[OPT], uz[OPT], tv[OPT];

    // ================= scalar branch =================
    // dd = vsdir_weight @ x_c
    #pragma unroll
    for (int j = 0; j < OP2; j++) { aX[j] = 0ull; aY[j] = 0ull; aZ[j] = 0ull; }
    #pragma unroll 2
    for (int c = 0; c < CC; c++) {
        float xx = A[(3 * c + 0) * TN + nl];
        float xy = A[(3 * c + 1) * TN + nl];
        float xz = A[(3 * c + 2) * TN + nl];
        unsigned long long xx2, xy2, xz2;
        PACK_DUP(xx2, xx); PACK_DUP(xy2, xy); PACK_DUP(xz2, xz);
        unsigned long long w2[OP2]; load_w4x2(&g_vsdWt[c * CC + ob], w2);
        #pragma unroll
        for (int j = 0; j < OP2; j++) {
            FMA2(aX[j], w2[j], xx2);
            FMA2(aY[j], w2[j], xy2);
            FMA2(aZ[j], w2[j], xz2);
        }
    }
    #pragma unroll
    for (int j = 0; j < OP2; j++) {
        ux[2*j] = lo2(aX[j]); ux[2*j+1] = hi2(aX[j]);
        uy[2*j] = lo2(aY[j]); uy[2*j+1] = hi2(aY[j]);
        uz[2*j] = lo2(aZ[j]); uz[2*j+1] = hi2(aZ[j]);
    }
    {
        float pq = 0;
        #pragma unroll
        for (int j = 0; j < OPT; j++) {
            float n2 = ux[j] * ux[j] + uy[j] * uy[j] + uz[j] * uz[j];
            float inv = 1.f / fmaxf(sqrtf(n2), EPSV);
            int o = ob + j;
            float q = (A[(3 * o + 0) * TN + nl] * ux[j] +
                       A[(3 * o + 1) * TN + nl] * uy[j] +
                       A[(3 * o + 2) * TN + nl] * uz[j]) * inv;
            tv[j] = q;
            pq += q * q;
        }
        red[og * TN + nl] = pq;
    }
    __syncthreads();
    float Q = 0;
    #pragma unroll
    for (int g = 0; g < NG; g++) Q += red[g * TN + nl];
    __syncthreads();
    const float qinv = 1.f / fmaxf(sqrtf(Q), EPSV);
    #pragma unroll
    for (int j = 0; j < OPT; j++)
        Bm[(CC + ob + j) * TN + nl] = tv[j] * qinv;
    __syncthreads();

    // s_out = vs_W @ p + vs_b + ss_W @ s + ss_b
    {
        unsigned long long so2[OP2];
        #pragma unroll
        for (int j = 0; j < OP2; j++)
            so2[j] = pack2(vs_b[ob + 2*j]     + ss_b[ob + 2*j],
                           vs_b[ob + 2*j + 1] + ss_b[ob + 2*j + 1]);
        #pragma unroll 2
        for (int c = 0; c < CC; c++) {
            float p = Bm[(CC + c) * TN + nl];
            float s = Bm[c * TN + nl];
            unsigned long long p2, s2;
            PACK_DUP(p2, p); PACK_DUP(s2, s);
            unsigned long long wva[OP2], wvb[OP2];
            load_w4x2(&g_vsWt[c * CC + ob], wva);
            load_w4x2(&g_ssWt[c * CC + ob], wvb);
            #pragma unroll
            for (int j = 0; j < OP2; j++) {
                FMA2(so2[j], wva[j], p2);
                FMA2(so2[j], wvb[j], s2);
            }
        }
        float* outs = out + (size_t)B * CC * 3 * NPTS + ((size_t)b * CC) * NPTS + n0 + nl;
        #pragma unroll
        for (int j = 0; j < OP2; j++) {
            outs[(size_t)(ob + 2*j) * NPTS]     = lo2(so2[j]);
            outs[(size_t)(ob + 2*j + 1) * NPTS] = hi2(so2[j]);
        }
    }

    // ---- t = sv_W @ s + sv_b ----
    {
        unsigned long long t2[OP2];
        #pragma unroll
        for (int j = 0; j < OP2; j++)
            t2[j] = pack2(sv_b[ob + 2*j], sv_b[ob + 2*j + 1]);
        #pragma unroll 2
        for (int c = 0; c < CC; c++) {
            float s = Bm[c * TN + nl];
            unsigned long long s2; PACK_DUP(s2, s);
            unsigned long long w2[OP2]; load_w4x2(&g_svWt[c * CC + ob], w2);
            #pragma unroll
            for (int j = 0; j < OP2; j++) FMA2(t2[j], w2[j], s2);
        }
        #pragma unroll
        for (int j = 0; j < OP2; j++) { tv[2*j] = lo2(t2[j]); tv[2*j+1] = hi2(t2[j]); }
    }

    // ================= vector branch =================
    // ---- u_c = W1 @ x_c ----
    #pragma unroll
    for (int j = 0; j < OP2; j++) { aX[j] = 0ull; aY[j] = 0ull; aZ[j] = 0ull; }
    #pragma unroll 2
    for (int c = 0; c < CC; c++) {
        float xx = A[(3 * c + 0) * TN + nl];
        float xy = A[(3 * c + 1) * TN + nl];
        float xz = A[(3 * c + 2) * TN + nl];
        unsigned long long xx2, xy2, xz2;
        PACK_DUP(xx2, xx); PACK_DUP(xy2, xy); PACK_DUP(xz2, xz);
        unsigned long long w2[OP2]; load_w4x2(&g_W1t[c * CC + ob], w2);
        #pragma unroll
        for (int j = 0; j < OP2; j++) {
            FMA2(aX[j], w2[j], xx2);
            FMA2(aY[j], w2[j], xy2);
            FMA2(aZ[j], w2[j], xz2);
        }
    }
    #pragma unroll
    for (int j = 0; j < OP2; j++) {
        ux[2*j] = lo2(aX[j]); ux[2*j+1] = hi2(aX[j]);
        uy[2*j] = lo2(aY[j]); uy[2*j+1] = hi2(aY[j]);
        uz[2*j] = lo2(aZ[j]); uz[2*j+1] = hi2(aZ[j]);
    }
    {
        float px = 0, py = 0, pz = 0, pt = 0;
        #pragma unroll
        for (int j = 0; j < OPT; j++) { px += ux[j]; py += uy[j]; pz += uz[j]; pt += tv[j] * tv[j]; }
        red[(og * 6 + 0) * TN + nl] = px; red[(og * 6 + 1) * TN + nl] = py;
        red[(og * 6 + 2) * TN + nl] = pz; red[(og * 6 + 3) * TN + nl] = pt;
    }
    __syncthreads();
    float mux = 0, muy = 0, muz = 0, tss = 0;
    #pragma unroll
    for (int g = 0; g < NG; g++) {
        mux += red[(g * 6 + 0) * TN + nl]; muy += red[(g * 6 + 1) * TN + nl];
        muz += red[(g * 6 + 2) * TN + nl]; tss += red[(g * 6 + 3) * TN + nl];
    }
    __syncthreads();
    mux *= (1.f / CC); muy *= (1.f / CC); muz *= (1.f / CC);
    const float tinv = 1.f / fmaxf(sqrtf(tss), EPSV);

    // v1 = (u_c - mu)*s2v + (mu + m) -> Bm; partial v1-mean
    float p1x = 0, p1y = 0, p1z = 0;
    #pragma unroll
    for (int j = 0; j < OPT; j++) {
        float s2v = tv[j] * tinv;
        float ax = fmaf(ux[j] - mux, s2v, mux + mx);
        float ay = fmaf(uy[j] - muy, s2v, muy + my);
        float az = fmaf(uz[j] - muz, s2v, muz + mz);
        int o = ob + j;
        Bm[(3 * o + 0) * TN + nl] = ax;
        Bm[(3 * o + 1) * TN + nl] = ay;
        Bm[(3 * o + 2) * TN + nl] = az;
        p1x += ax; p1y += ay; p1z += az;
    }

    // ---- d_c = W2 @ x_c ----
    #pragma unroll
    for (int j = 0; j < OP2; j++) { aX[j] = 0ull; aY[j] = 0ull; aZ[j] = 0ull; }
    #pragma unroll 2
    for (int c = 0; c < CC; c++) {
        float xx = A[(3 * c + 0) * TN + nl];
        float xy = A[(3 * c + 1) * TN + nl];
        float xz = A[(3 * c + 2) * TN + nl];
        unsigned long long xx2, xy2, xz2;
        PACK_DUP(xx2, xx); PACK_DUP(xy2, xy); PACK_DUP(xz2, xz);
        unsigned long long w2[OP2]; load_w4x2(&g_W2t[c * CC + ob], w2);
        #pragma unroll
        for (int j = 0; j < OP2; j++) {
            FMA2(aX[j], w2[j], xx2);
            FMA2(aY[j], w2[j], xy2);
            FMA2(aZ[j], w2[j], xz2);
        }
    }
    #pragma unroll
    for (int j = 0; j < OP2; j++) {
        ux[2*j] = lo2(aX[j]); ux[2*j+1] = hi2(aX[j]);
        uy[2*j] = lo2(aY[j]); uy[2*j+1] = hi2(aY[j]);
        uz[2*j] = lo2(aZ[j]); uz[2*j+1] = hi2(aZ[j]);
    }
    {
        float px = 0, py = 0, pz = 0;
        #pragma unroll
        for (int j = 0; j < OPT; j++) { px += ux[j]; py += uy[j]; pz += uz[j]; }
        red[(og * 6 + 0) * TN + nl] = px;  red[(og * 6 + 1) * TN + nl] = py;
        red[(og * 6 + 2) * TN + nl] = pz;  red[(og * 6 + 3) * TN + nl] = p1x;
        red[(og * 6 + 4) * TN + nl] = p1y; red[(og * 6 + 5) * TN + nl] = p1z;
    }
    __syncthreads();
    float dmx = 0, dmy = 0, dmz = 0, m1x = 0, m1y = 0, m1z = 0;
    #pragma unroll
    for (int g = 0; g < NG; g++) {
        dmx += red[(g * 6 + 0) * TN + nl]; dmy += red[(g * 6 + 1) * TN + nl];
        dmz += red[(g * 6 + 2) * TN + nl]; m1x += red[(g * 6 + 3) * TN + nl];
        m1y += red[(g * 6 + 4) * TN + nl]; m1z += red[(g * 6 + 5) * TN + nl];
    }
    __syncthreads();
    dmx *= (1.f / CC); dmy *= (1.f / CC); dmz *= (1.f / CC);
    m1x *= (1.f / CC); m1y *= (1.f / CC); m1z *= (1.f / CC);

    float ny[OPT];
    {
        float pl = 0;
        #pragma unroll
        for (int j = 0; j < OPT; j++) {
            ux[j] -= dmx; uy[j] -= dmy; uz[j] -= dmz;
            float n2 = ux[j] * ux[j] + uy[j] * uy[j] + uz[j] * uz[j];
            ny[j] = sqrtf(n2);
            pl += n2;
        }
        red[og * TN + nl] = pl;
    }
    __syncthreads();
    float L = 0;
    #pragma unroll
    for (int g = 0; g < NG; g++) L += red[g * TN + nl];
    __syncthreads();
    const float linv = 1.f / fmaxf(sqrtf(L), EPSV);

    // ---- v_cross -> A ----
    #pragma unroll
    for (int j = 0; j < OPT; j++) {
        float cf = (ny[j] * linv) / fmaxf(ny[j], EPSV);
        float ex = ux[j] * cf, ey = uy[j] * cf, ez = uz[j] * cf;
        int o = ob + j;
        float ax = Bm[(3 * o + 0) * TN + nl];
        float ay = Bm[(3 * o + 1) * TN + nl];
        float az = Bm[(3 * o + 2) * TN + nl];
        float wx = ax - m1x, wy = ay - m1y, wz = az - m1z;
        A[(3 * o + 0) * TN + nl] = ey * wz - ez * wy + ax;
        A[(3 * o + 1) * TN + nl] = ez * wx - ex * wz + ay;
        A[(3 * o + 2) * TN + nl] = ex * wy - ey * wx + az;
    }
    __syncthreads();

    // ---- v_out = W3[:, :128] @ v_cross (A) + W3[:, 128:] @ v1 (Bm) ----
    #pragma unroll
    for (int j = 0; j < OP2; j++) { aX[j] = 0ull; aY[j] = 0ull; aZ[j] = 0ull; }
    #pragma unroll 2
    for (int c = 0; c < CC; c++) {
        float xx = A[(3 * c + 0) * TN + nl];
        float xy = A[(3 * c + 1) * TN + nl];
        float xz = A[(3 * c + 2) * TN + nl];
        unsigned long long xx2, xy2, xz2;
        PACK_DUP(xx2, xx); PACK_DUP(xy2, xy); PACK_DUP(xz2, xz);
        unsigned long long w2[OP2]; load_w4x2(&g_W3t[c * CC + ob], w2);
        #pragma unroll
        for (int j = 0; j < OP2; j++) {
            FMA2(aX[j], w2[j], xx2);
            FMA2(aY[j], w2[j], xy2);
            FMA2(aZ[j], w2[j], xz2);
        }
    }
    #pragma unroll 2
    for (int c = 0; c < CC; c++) {
        float xx = Bm[(3 * c + 0) * TN + nl];
        float xy = Bm[(3 * c + 1) * TN + nl];
        float xz = Bm[(3 * c + 2) * TN + nl];
        unsigned long long xx2, xy2, xz2;
        PACK_DUP(xx2, xx); PACK_DUP(xy2, xy); PACK_DUP(xz2, xz);
        unsigned long long w2[OP2]; load_w4x2(&g_W3t[(CC + c) * CC + ob], w2);
        #pragma unroll
        for (int j = 0; j < OP2; j++) {
            FMA2(aX[j], w2[j], xx2);
            FMA2(aY[j], w2[j], xy2);
            FMA2(aZ[j], w2[j], xz2);
        }
    }
    {
        float* outv = out + ((size_t)b * CC) * 3 * NPTS + n0 + nl;
        #pragma unroll
        for (int j = 0; j < OP2; j++) {
            int o = ob + 2 * j;
            outv[(size_t)(3 * o + 0) * NPTS] = lo2(aX[j]);
            outv[(size_t)(3 * o + 1) * NPTS] = lo2(aY[j]);
            outv[(size_t)(3 * o + 2) * NPTS] = lo2(aZ[j]);
            outv[(size_t)(3 * o + 3) * NPTS] = hi2(aX[j]);
            outv[(size_t)(3 * o + 4) * NPTS] = hi2(aY[j]);
            outv[(size_t)(3 * o + 5) * NPTS] = hi2(aZ[j]);
        }
    }
}

extern "C" void kernel_launch(void* const* d_in, const int* in_sizes, int n_in,
                              void* d_out, int out_size)
{
    const float* v_in      = (const float*)d_in[0];
    const float* s_in      = (const float*)d_in[1];
    const float* weight    = (const float*)d_in[2];
    const float* sv_W      = (const float*)d_in[3];
    const float* sv_b      = (const float*)d_in[4];
    const float* cross_w   = (const float*)d_in[5];
    const float* crossfc_w = (const float*)d_in[6];
    const float* vsdir_w   = (const float*)d_in[7];
    const float* vs_W      = (const float*)d_in[8];
    const float* vs_b      = (const float*)d_in[9];
    const float* ss_W      = (const float*)d_in[10];
    const float* ss_b      = (const float*)d_in[11];
    float* out = (float*)d_out;

    const int B = in_sizes[0] / (CC * 3 * NPTS);   // 16

    prep_kernel<<<CC, CC>>>(weight, sv_W, cross_w, crossfc_w, vsdir_w, vs_W, ss_W);

    // Actual use: 6*CC*TN + 96*TN floats = 110,592 B. Request 120KB so only
    // one block fits per SM -> ~108KB of L1D remains for weight caching.
    const size_t smem = 122880;
    cudaFuncSetAttribute(fused_kernel, cudaFuncAttributeMaxDynamicSharedMemorySize, (int)smem);
    fused_kernel<<<16 * (NPTS / TN), NTHR, smem>>>(v_in, s_in, sv_b, vs_b, ss_b, out, B);
}

// round 8
// speedup vs baseline: 1.1985x; 1.1985x over previous
#include <cuda_runtime.h>
#include <math.h>
#include <stdint.h>

#define CC   128
#define NPTS 4096
#define TN   64
#define NG   8
#define OPT  16
#define OP2  8
#define NSL  2
#define NTHR 256
#define EPSV 1e-12f

typedef unsigned long long ull;

// Pre-expanded (se3) + transposed weights: Wt[c][o] = W[o][c]
__device__ float g_W1t [CC * CC];
__device__ float g_W2t [CC * CC];
__device__ float g_W3t [2 * CC * CC];
__device__ float g_svWt[CC * CC];
__device__ float g_vsdWt[CC * CC];
__device__ float g_vsWt[CC * CC];
__device__ float g_ssWt[CC * CC];

__global__ void prep_kernel(const float* __restrict__ weight,
                            const float* __restrict__ sv_W,
                            const float* __restrict__ cross_weight,
                            const float* __restrict__ crossfc_weight,
                            const float* __restrict__ vsdir_weight,
                            const float* __restrict__ vs_W,
                            const float* __restrict__ ss_W)
{
    const int o = blockIdx.x;
    const int t = threadIdx.x;
    __shared__ float sred[128];

    float w = (t < CC - 1) ? weight[o * (CC - 1) + t] : 0.f;
    sred[t] = w; __syncthreads();
    for (int k = 64; k > 0; k >>= 1) { if (t < k) sred[t] += sred[t + k]; __syncthreads(); }
    float rs1 = sred[0]; __syncthreads();
    if (t < CC - 1) g_W1t[t * CC + o] = w;
    else            g_W1t[(CC - 1) * CC + o] = 1.f - rs1;

    float w2 = (t < CC - 1) ? cross_weight[o * (CC - 1) + t] : 0.f;
    sred[t] = w2; __syncthreads();
    for (int k = 64; k > 0; k >>= 1) { if (t < k) sred[t] += sred[t + k]; __syncthreads(); }
    float rs2 = sred[0]; __syncthreads();
    if (t < CC - 1) g_W2t[t * CC + o] = w2;
    else            g_W2t[(CC - 1) * CC + o] = 1.f - rs2;

    float a0 = crossfc_weight[o * (2 * CC - 1) + t];
    float a1 = (t < CC - 1) ? crossfc_weight[o * (2 * CC - 1) + CC + t] : 0.f;
    sred[t] = a0 + a1; __syncthreads();
    for (int k = 64; k > 0; k >>= 1) { if (t < k) sred[t] += sred[t + k]; __syncthreads(); }
    float rs3 = sred[0]; __syncthreads();
    g_W3t[t * CC + o] = a0;
    if (t < CC - 1) g_W3t[(CC + t) * CC + o] = a1;
    else            g_W3t[(2 * CC - 1) * CC + o] = 1.f - rs3;

    g_svWt [t * CC + o] = sv_W        [o * CC + t];
    g_vsdWt[t * CC + o] = vsdir_weight[o * CC + t];
    g_vsWt [t * CC + o] = vs_W        [o * CC + t];
    g_ssWt [t * CC + o] = ss_W        [o * CC + t];
}

// ---- packed f32x2 helpers ----
#define FMA2(acc, w, x) \
    asm("fma.rn.f32x2 %0, %1, %2, %3;" : "=l"(acc) : "l"(w), "l"(x), "l"(acc))
#define ADD2(d, a, b) \
    asm("add.rn.f32x2 %0, %1, %2;" : "=l"(d) : "l"(a), "l"(b))
#define PACK_DUP(out, x) \
    asm("mov.b64 %0, {%1, %1};" : "=l"(out) : "r"(__float_as_uint(x)))

__device__ __forceinline__ float lo2(ull v) { return __uint_as_float((unsigned)v); }
__device__ __forceinline__ float hi2(ull v) { return __uint_as_float((unsigned)(v >> 32)); }
__device__ __forceinline__ ull pack2(float lo, float hi) {
    return (ull)__float_as_uint(lo) | ((ull)__float_as_uint(hi) << 32);
}
__device__ __forceinline__ ull lds2(const float* p) { return *(const ull*)p; }
__device__ __forceinline__ void sts2(float* p, ull v) { *(ull*)p = v; }

// Load 16 consecutive transposed-weight floats as 8 packed u64 (4x LDG.128).
__device__ __forceinline__ void load_w8x2(const float* __restrict__ base, ull* w2)
{
    const ulonglong2* p = (const ulonglong2*)base;
    ulonglong2 a = p[0], b = p[1], c = p[2], d = p[3];
    w2[0] = a.x; w2[1] = a.y; w2[2] = b.x; w2[3] = b.y;
    w2[4] = c.x; w2[5] = c.y; w2[6] = d.x; w2[7] = d.y;
}

// GEMM over 3-vector tile S[384][TN]; accumulate 16 out-ch x 3 comps x 2 slots.
template<bool INIT>
__device__ __forceinline__ void gemm3(const float* __restrict__ Wt,
                                      const float* __restrict__ S,
                                      int cb, int ob,
                                      ull aX[NSL][OP2], ull aY[NSL][OP2], ull aZ[NSL][OP2])
{
    if (INIT) {
        #pragma unroll
        for (int s = 0; s < NSL; s++)
            #pragma unroll
            for (int j = 0; j < OP2; j++) { aX[s][j] = 0; aY[s][j] = 0; aZ[s][j] = 0; }
    }
    #pragma unroll 2
    for (int c = 0; c < CC; c++) {
        ull xp = lds2(&S[(3 * c + 0) * TN + cb]);
        ull yp = lds2(&S[(3 * c + 1) * TN + cb]);
        ull zp = lds2(&S[(3 * c + 2) * TN + cb]);
        ull x0, x1, y0, y1, z0, z1;
        PACK_DUP(x0, lo2(xp)); PACK_DUP(x1, hi2(xp));
        PACK_DUP(y0, lo2(yp)); PACK_DUP(y1, hi2(yp));
        PACK_DUP(z0, lo2(zp)); PACK_DUP(z1, hi2(zp));
        ull w2[OP2]; load_w8x2(&Wt[c * CC + ob], w2);
        #pragma unroll
        for (int j = 0; j < OP2; j++) {
            FMA2(aX[0][j], w2[j], x0); FMA2(aX[1][j], w2[j], x1);
            FMA2(aY[0][j], w2[j], y0); FMA2(aY[1][j], w2[j], y1);
            FMA2(aZ[0][j], w2[j], z0); FMA2(aZ[1][j], w2[j], z1);
        }
    }
}

// value of channel (ob + jj) for slot s from packed accumulators
#define GETA(arr, s, jj) ((jj & 1) ? hi2(arr[s][jj >> 1]) : lo2(arr[s][jj >> 1]))

// ---------------------------------------------------------------------------
// Fused kernel: one block = one (b, 64-point) tile. 256 threads, 1 block/SM.
// Each thread: 16 output channels (og) x 2 adjacent points (cb, cb+1).
// ---------------------------------------------------------------------------
__global__ void __launch_bounds__(NTHR, 1)
fused_kernel(const float* __restrict__ v_in, const float* __restrict__ s_in,
             const float* __restrict__ sv_b, const float* __restrict__ vs_b,
             const float* __restrict__ ss_b, float* __restrict__ out, int B)
{
    extern __shared__ float sm[];
    float* A   = sm;                     // [384][64]  x_c, later v_cross
    float* Bm  = sm + 3 * CC * TN;       // [384][64]  s+p, later v1
    float* red = sm + 6 * CC * TN;       // [48][64]

    const int tid = threadIdx.x;
    const int nl  = tid & 31;
    const int og  = tid >> 5;            // 0..7
    const int ob  = og * OPT;
    const int cb  = nl * 2;              // column base (2 adjacent points)

    const int b  = blockIdx.x >> 6;      // 64 tiles per batch
    const int n0 = (blockIdx.x & 63) * TN;

    // ---- load x -> A, s -> Bm[0:128] (coalesced over 64 cols) ----
    {
        const int colg = tid & 63;
        const int rq   = tid >> 6;       // 0..3
        const float* src = v_in + ((size_t)b * (3 * CC)) * NPTS + n0 + colg;
        #pragma unroll 4
        for (int it = 0; it < 96; it++) {
            int r = rq + it * 4;
            A[r * TN + colg] = src[(size_t)r * NPTS];
        }
        const float* ssrc = s_in + ((size_t)b * CC) * NPTS + n0 + colg;
        #pragma unroll 4
        for (int it = 0; it < 32; it++) {
            int r = rq + it * 4;
            Bm[r * TN + colg] = ssrc[(size_t)r * NPTS];
        }
    }
    __syncthreads();

    // ---- x channel mean; center A in place ----
    float mx[NSL], my[NSL], mz[NSL];
    {
        ull px2 = 0, py2 = 0, pz2 = 0;
        #pragma unroll
        for (int j = 0; j < OPT; j++) {
            int c = ob + j;
            ADD2(px2, px2, lds2(&A[(3 * c + 0) * TN + cb]));
            ADD2(py2, py2, lds2(&A[(3 * c + 1) * TN + cb]));
            ADD2(pz2, pz2, lds2(&A[(3 * c + 2) * TN + cb]));
        }
        sts2(&red[(og * 6 + 0) * TN + cb], px2);
        sts2(&red[(og * 6 + 1) * TN + cb], py2);
        sts2(&red[(og * 6 + 2) * TN + cb], pz2);
    }
    __syncthreads();
    ull mx2 = 0, my2 = 0, mz2 = 0;
    #pragma unroll
    for (int g = 0; g < NG; g++) {
        ADD2(mx2, mx2, lds2(&red[(g * 6 + 0) * TN + cb]));
        ADD2(my2, my2, lds2(&red[(g * 6 + 1) * TN + cb]));
        ADD2(mz2, mz2, lds2(&red[(g * 6 + 2) * TN + cb]));
    }
    __syncthreads();
    #pragma unroll
    for (int s = 0; s < NSL; s++) {
        mx[s] = (s ? hi2(mx2) : lo2(mx2)) * (1.f / CC);
        my[s] = (s ? hi2(my2) : lo2(my2)) * (1.f / CC);
        mz[s] = (s ? hi2(mz2) : lo2(mz2)) * (1.f / CC);
    }
    {
        ull nmx = pack2(-mx[0], -mx[1]), nmy = pack2(-my[0], -my[1]), nmz = pack2(-mz[0], -mz[1]);
        #pragma unroll
        for (int j = 0; j < OPT; j++) {
            int c = ob + j;
            ull v;
            v = lds2(&A[(3 * c + 0) * TN + cb]); ADD2(v, v, nmx); sts2(&A[(3 * c + 0) * TN + cb], v);
            v = lds2(&A[(3 * c + 1) * TN + cb]); ADD2(v, v, nmy); sts2(&A[(3 * c + 1) * TN + cb], v);
            v = lds2(&A[(3 * c + 2) * TN + cb]); ADD2(v, v, nmz); sts2(&A[(3 * c + 2) * TN + cb], v);
        }
    }
    __syncthreads();

    ull aX[NSL][OP2], aY[NSL][OP2], aZ[NSL][OP2];

    // ================= scalar branch =================
    // dd = vsdir_weight @ x_c
    gemm3<true>(g_vsdWt, A, cb, ob, aX, aY, aZ);
    float tvv[NSL][OPT];
    {
        float pq[NSL] = {0.f, 0.f};
        #pragma unroll
        for (int jj = 0; jj < OPT; jj++) {
            int o = ob + jj;
            ull xp = lds2(&A[(3 * o + 0) * TN + cb]);
            ull yp = lds2(&A[(3 * o + 1) * TN + cb]);
            ull zp = lds2(&A[(3 * o + 2) * TN + cb]);
            #pragma unroll
            for (int s = 0; s < NSL; s++) {
                float ux = GETA(aX, s, jj), uy = GETA(aY, s, jj), uz = GETA(aZ, s, jj);
                float n2 = ux * ux + uy * uy + uz * uz;
                float inv = 1.f / fmaxf(sqrtf(n2), EPSV);
                float vx = s ? hi2(xp) : lo2(xp);
                float vy = s ? hi2(yp) : lo2(yp);
                float vz = s ? hi2(zp) : lo2(zp);
                float q = (vx * ux + vy * uy + vz * uz) * inv;
                tvv[s][jj] = q;
                pq[s] += q * q;
            }
        }
        sts2(&red[og * TN + cb], pack2(pq[0], pq[1]));
    }
    __syncthreads();
    ull Q2 = 0;
    #pragma unroll
    for (int g = 0; g < NG; g++) ADD2(Q2, Q2, lds2(&red[g * TN + cb]));
    __syncthreads();
    {
        float qinv[NSL];
        qinv[0] = 1.f / fmaxf(sqrtf(lo2(Q2)), EPSV);
        qinv[1] = 1.f / fmaxf(sqrtf(hi2(Q2)), EPSV);
        #pragma unroll
        for (int jj = 0; jj < OPT; jj++)
            sts2(&Bm[(CC + ob + jj) * TN + cb], pack2(tvv[0][jj] * qinv[0], tvv[1][jj] * qinv[1]));
    }
    __syncthreads();

    // s_out = vs_W @ p + vs_b + ss_W @ s + ss_b
    {
        ull so2[NSL][OP2];
        #pragma unroll
        for (int j = 0; j < OP2; j++) {
            ull bj = pack2(vs_b[ob + 2 * j] + ss_b[ob + 2 * j],
                           vs_b[ob + 2 * j + 1] + ss_b[ob + 2 * j + 1]);
            so2[0][j] = bj; so2[1][j] = bj;
        }
        #pragma unroll 2
        for (int c = 0; c < CC; c++) {
            ull pp = lds2(&Bm[(CC + c) * TN + cb]);
            ull sp = lds2(&Bm[c * TN + cb]);
            ull p0, p1, s0, s1;
            PACK_DUP(p0, lo2(pp)); PACK_DUP(p1, hi2(pp));
            PACK_DUP(s0, lo2(sp)); PACK_DUP(s1, hi2(sp));
            ull wva[OP2], wvb[OP2];
            load_w8x2(&g_vsWt[c * CC + ob], wva);
            load_w8x2(&g_ssWt[c * CC + ob], wvb);
            #pragma unroll
            for (int j = 0; j < OP2; j++) {
                FMA2(so2[0][j], wva[j], p0); FMA2(so2[1][j], wva[j], p1);
                FMA2(so2[0][j], wvb[j], s0); FMA2(so2[1][j], wvb[j], s1);
            }
        }
        float* outs = out + (size_t)B * CC * 3 * NPTS + ((size_t)b * CC) * NPTS + n0 + cb;
        #pragma unroll
        for (int j = 0; j < OP2; j++) {
            *(ull*)&outs[(size_t)(ob + 2 * j) * NPTS]     = pack2(lo2(so2[0][j]), lo2(so2[1][j]));
            *(ull*)&outs[(size_t)(ob + 2 * j + 1) * NPTS] = pack2(hi2(so2[0][j]), hi2(so2[1][j]));
        }
    }

    // ---- t = sv_W @ s + sv_b ----
    ull t2[NSL][OP2];
    {
        #pragma unroll
        for (int j = 0; j < OP2; j++) {
            ull bj = pack2(sv_b[ob + 2 * j], sv_b[ob + 2 * j + 1]);
            t2[0][j] = bj; t2[1][j] = bj;
        }
        #pragma unroll 2
        for (int c = 0; c < CC; c++) {
            ull sp = lds2(&Bm[c * TN + cb]);
            ull s0, s1;
            PACK_DUP(s0, lo2(sp)); PACK_DUP(s1, hi2(sp));
            ull w2[OP2]; load_w8x2(&g_svWt[c * CC + ob], w2);
            #pragma unroll
            for (int j = 0; j < OP2; j++) {
                FMA2(t2[0][j], w2[j], s0); FMA2(t2[1][j], w2[j], s1);
            }
        }
    }

    // ================= vector branch =================
    // ---- u_c = W1 @ x_c ----
    gemm3<true>(g_W1t, A, cb, ob, aX, aY, aZ);
    {
        ull px2 = 0, py2 = 0, pz2 = 0, pt2 = 0;
        #pragma unroll
        for (int j = 0; j < OP2; j++) {
            ADD2(px2, px2, aX[0][j]);  // packed over channel pairs: need per-slot
        }
        // redo per-slot properly: sum channels within each slot
        float pu[NSL][4];
        #pragma unroll
        for (int s = 0; s < NSL; s++) {
            ull sx = 0, sy = 0, sz = 0, st = 0;
            #pragma unroll
            for (int j = 0; j < OP2; j++) {
                ADD2(sx, sx, aX[s][j]); ADD2(sy, sy, aY[s][j]); ADD2(sz, sz, aZ[s][j]);
                FMA2(st, t2[s][j], t2[s][j]);
            }
            pu[s][0] = lo2(sx) + hi2(sx); pu[s][1] = lo2(sy) + hi2(sy);
            pu[s][2] = lo2(sz) + hi2(sz); pu[s][3] = lo2(st) + hi2(st);
        }
        sts2(&red[(og * 6 + 0) * TN + cb], pack2(pu[0][0], pu[1][0]));
        sts2(&red[(og * 6 + 1) * TN + cb], pack2(pu[0][1], pu[1][1]));
        sts2(&red[(og * 6 + 2) * TN + cb], pack2(pu[0][2], pu[1][2]));
        sts2(&red[(og * 6 + 3) * TN + cb], pack2(pu[0][3], pu[1][3]));
        (void)px2; (void)py2; (void)pz2; (void)pt2;
    }
    __syncthreads();
    float mux[NSL], muy[NSL], muz[NSL], tinv[NSL];
    {
        ull sx = 0, sy = 0, sz = 0, st = 0;
        #pragma unroll
        for (int g = 0; g < NG; g++) {
            ADD2(sx, sx, lds2(&red[(g * 6 + 0) * TN + cb]));
            ADD2(sy, sy, lds2(&red[(g * 6 + 1) * TN + cb]));
            ADD2(sz, sz, lds2(&red[(g * 6 + 2) * TN + cb]));
            ADD2(st, st, lds2(&red[(g * 6 + 3) * TN + cb]));
        }
        #pragma unroll
        for (int s = 0; s < NSL; s++) {
            mux[s] = (s ? hi2(sx) : lo2(sx)) * (1.f / CC);
            muy[s] = (s ? hi2(sy) : lo2(sy)) * (1.f / CC);
            muz[s] = (s ? hi2(sz) : lo2(sz)) * (1.f / CC);
            tinv[s] = 1.f / fmaxf(sqrtf(s ? hi2(st) : lo2(st)), EPSV);
        }
    }
    __syncthreads();

    // v1 = (u_c - mu)*s2v + (mu + m) -> Bm; partial v1-mean
    float p1x[NSL] = {0.f, 0.f}, p1y[NSL] = {0.f, 0.f}, p1z[NSL] = {0.f, 0.f};
    #pragma unroll
    for (int jj = 0; jj < OPT; jj++) {
        int o = ob + jj;
        float a0x, a0y, a0z, a1x, a1y, a1z;
        {
            float s2v = ((jj & 1) ? hi2(t2[0][jj >> 1]) : lo2(t2[0][jj >> 1])) * tinv[0];
            a0x = fmaf(GETA(aX, 0, jj) - mux[0], s2v, mux[0] + mx[0]);
            a0y = fmaf(GETA(aY, 0, jj) - muy[0], s2v, muy[0] + my[0]);
            a0z = fmaf(GETA(aZ, 0, jj) - muz[0], s2v, muz[0] + mz[0]);
            p1x[0] += a0x; p1y[0] += a0y; p1z[0] += a0z;
        }
        {
            float s2v = ((jj & 1) ? hi2(t2[1][jj >> 1]) : lo2(t2[1][jj >> 1])) * tinv[1];
            a1x = fmaf(GETA(aX, 1, jj) - mux[1], s2v, mux[1] + mx[1]);
            a1y = fmaf(GETA(aY, 1, jj) - muy[1], s2v, muy[1] + my[1]);
            a1z = fmaf(GETA(aZ, 1, jj) - muz[1], s2v, muz[1] + mz[1]);
            p1x[1] += a1x; p1y[1] += a1y; p1z[1] += a1z;
        }
        sts2(&Bm[(3 * o + 0) * TN + cb], pack2(a0x, a1x));
        sts2(&Bm[(3 * o + 1) * TN + cb], pack2(a0y, a1y));
        sts2(&Bm[(3 * o + 2) * TN + cb], pack2(a0z, a1z));
    }

    // ---- d_c = W2 @ x_c ----
    gemm3<true>(g_W2t, A, cb, ob, aX, aY, aZ);
    {
        float pd[NSL][3];
        #pragma unroll
        for (int s = 0; s < NSL; s++) {
            ull sx = 0, sy = 0, sz = 0;
            #pragma unroll
            for (int j = 0; j < OP2; j++) {
                ADD2(sx, sx, aX[s][j]); ADD2(sy, sy, aY[s][j]); ADD2(sz, sz, aZ[s][j]);
            }
            pd[s][0] = lo2(sx) + hi2(sx); pd[s][1] = lo2(sy) + hi2(sy); pd[s][2] = lo2(sz) + hi2(sz);
        }
        sts2(&red[(og * 6 + 0) * TN + cb], pack2(pd[0][0], pd[1][0]));
        sts2(&red[(og * 6 + 1) * TN + cb], pack2(pd[0][1], pd[1][1]));
        sts2(&red[(og * 6 + 2) * TN + cb], pack2(pd[0][2], pd[1][2]));
        sts2(&red[(og * 6 + 3) * TN + cb], pack2(p1x[0], p1x[1]));
        sts2(&red[(og * 6 + 4) * TN + cb], pack2(p1y[0], p1y[1]));
        sts2(&red[(og * 6 + 5) * TN + cb], pack2(p1z[0], p1z[1]));
    }
    __syncthreads();
    float dmx[NSL], dmy[NSL], dmz[NSL], m1x[NSL], m1y[NSL], m1z[NSL];
    {
        ull sx = 0, sy = 0, sz = 0, s1x = 0, s1y = 0, s1z = 0;
        #pragma unroll
        for (int g = 0; g < NG; g++) {
            ADD2(sx,  sx,  lds2(&red[(g * 6 + 0) * TN + cb]));
            ADD2(sy,  sy,  lds2(&red[(g * 6 + 1) * TN + cb]));
            ADD2(sz,  sz,  lds2(&red[(g * 6 + 2) * TN + cb]));
            ADD2(s1x, s1x, lds2(&red[(g * 6 + 3) * TN + cb]));
            ADD2(s1y, s1y, lds2(&red[(g * 6 + 4) * TN + cb]));
            ADD2(s1z, s1z, lds2(&red[(g * 6 + 5) * TN + cb]));
        }
        #pragma unroll
        for (int s = 0; s < NSL; s++) {
            dmx[s] = (s ? hi2(sx)  : lo2(sx))  * (1.f / CC);
            dmy[s] = (s ? hi2(sy)  : lo2(sy))  * (1.f / CC);
            dmz[s] = (s ? hi2(sz)  : lo2(sz))  * (1.f / CC);
            m1x[s] = (s ? hi2(s1x) : lo2(s1x)) * (1.f / CC);
            m1y[s] = (s ? hi2(s1y) : lo2(s1y)) * (1.f / CC);
            m1z[s] = (s ? hi2(s1z) : lo2(s1z)) * (1.f / CC);
        }
    }
    __syncthreads();

    // ---- center d; per-channel n2; sumsq over channels ----
    ull nn2[NSL][OP2];
    {
        float pl[NSL];
        #pragma unroll
        for (int s = 0; s < NSL; s++) {
            ull ndx, ndy, ndz;
            PACK_DUP(ndx, -dmx[s]); PACK_DUP(ndy, -dmy[s]); PACK_DUP(ndz, -dmz[s]);
            ull plsum = 0;
            #pragma unroll
            for (int j = 0; j < OP2; j++) {
                ADD2(aX[s][j], aX[s][j], ndx);
                ADD2(aY[s][j], aY[s][j], ndy);
                ADD2(aZ[s][j], aZ[s][j], ndz);
                ull n2 = 0;
                FMA2(n2, aX[s][j], aX[s][j]);
                FMA2(n2, aY[s][j], aY[s][j]);
                FMA2(n2, aZ[s][j], aZ[s][j]);
                nn2[s][j] = n2;
                ADD2(plsum, plsum, n2);
            }
            pl[s] = lo2(plsum) + hi2(plsum);
        }
        sts2(&red[og * TN + cb], pack2(pl[0], pl[1]));
    }
    __syncthreads();
    float linv[NSL];
    {
        ull L2 = 0;
        #pragma unroll
        for (int g = 0; g < NG; g++) ADD2(L2, L2, lds2(&red[g * TN + cb]));
        linv[0] = 1.f / fmaxf(sqrtf(lo2(L2)), EPSV);
        linv[1] = 1.f / fmaxf(sqrtf(hi2(L2)), EPSV);
    }
    __syncthreads();

    // ---- v_cross = cross(ceq, v1 - v1m) + v1 -> A ----
    #pragma unroll
    for (int jj = 0; jj < OPT; jj++) {
        int o = ob + jj;
        ull v1xp = lds2(&Bm[(3 * o + 0) * TN + cb]);
        ull v1yp = lds2(&Bm[(3 * o + 1) * TN + cb]);
        ull v1zp = lds2(&Bm[(3 * o + 2) * TN + cb]);
        float cx[NSL], cy[NSL], cz[NSL];
        #pragma unroll
        for (int s = 0; s < NSL; s++) {
            float n2 = (jj & 1) ? hi2(nn2[s][jj >> 1]) : lo2(nn2[s][jj >> 1]);
            float nyv = sqrtf(n2);
            float cf = (nyv * linv[s]) / fmaxf(nyv, EPSV);
            float ex = GETA(aX, s, jj) * cf;
            float ey = GETA(aY, s, jj) * cf;
            float ez = GETA(aZ, s, jj) * cf;
            float ax = s ? hi2(v1xp) : lo2(v1xp);
            float ay = s ? hi2(v1yp) : lo2(v1yp);
            float az = s ? hi2(v1zp) : lo2(v1zp);
            float wx = ax - m1x[s], wy = ay - m1y[s], wz = az - m1z[s];
            cx[s] = ey * wz - ez * wy + ax;
            cy[s] = ez * wx - ex * wz + ay;
            cz[s] = ex * wy - ey * wx + az;
        }
        sts2(&A[(3 * o + 0) * TN + cb], pack2(cx[0], cx[1]));
        sts2(&A[(3 * o + 1) * TN + cb], pack2(cy[0], cy[1]));
        sts2(&A[(3 * o + 2) * TN + cb], pack2(cz[0], cz[1]));
    }
    __syncthreads();

    // ---- v_out = W3[:, :128] @ v_cross (A) + W3[:, 128:] @ v1 (Bm) ----
    gemm3<true >(g_W3t,           A,  cb, ob, aX, aY, aZ);
    gemm3<false>(g_W3t + CC * CC, Bm, cb, ob, aX, aY, aZ);
    {
        float* outv = out + ((size_t)b * CC) * 3 * NPTS + n0 + cb;
        #pragma unroll
        for (int j = 0; j < OP2; j++) {
            int o0 = ob + 2 * j, o1 = o0 + 1;
            *(ull*)&outv[(size_t)(3 * o0 + 0) * NPTS] = pack2(lo2(aX[0][j]), lo2(aX[1][j]));
            *(ull*)&outv[(size_t)(3 * o0 + 1) * NPTS] = pack2(lo2(aY[0][j]), lo2(aY[1][j]));
            *(ull*)&outv[(size_t)(3 * o0 + 2) * NPTS] = pack2(lo2(aZ[0][j]), lo2(aZ[1][j]));
            *(ull*)&outv[(size_t)(3 * o1 + 0) * NPTS] = pack2(hi2(aX[0][j]), hi2(aX[1][j]));
            *(ull*)&outv[(size_t)(3 * o1 + 1) * NPTS] = pack2(hi2(aY[0][j]), hi2(aY[1][j]));
            *(ull*)&outv[(size_t)(3 * o1 + 2) * NPTS] = pack2(hi2(aZ[0][j]), hi2(aZ[1][j]));
        }
    }
}

extern "C" void kernel_launch(void* const* d_in, const int* in_sizes, int n_in,
                              void* d_out, int out_size)
{
    const float* v_in      = (const float*)d_in[0];
    const float* s_in      = (const float*)d_in[1];
    const float* weight    = (const float*)d_in[2];
    const float* sv_W      = (const float*)d_in[3];
    const float* sv_b      = (const float*)d_in[4];
    const float* cross_w   = (const float*)d_in[5];
    const float* crossfc_w = (const float*)d_in[6];
    const float* vsdir_w   = (const float*)d_in[7];
    const float* vs_W      = (const float*)d_in[8];
    const float* vs_b      = (const float*)d_in[9];
    const float* ss_W      = (const float*)d_in[10];
    const float* ss_b      = (const float*)d_in[11];
    float* out = (float*)d_out;

    const int B = in_sizes[0] / (CC * 3 * NPTS);   // 16

    prep_kernel<<<CC, CC>>>(weight, sv_W, cross_w, crossfc_w, vsdir_w, vs_W, ss_W);

    // smem: 2 * 384*64 + 48*64 floats = 208,896 B -> 1 block/SM
    const size_t smem = (size_t)(6 * CC * TN + 48 * TN) * sizeof(float);
    cudaFuncSetAttribute(fused_kernel, cudaFuncAttributeMaxDynamicSharedMemorySize, (int)smem);
    fused_kernel<<<B * (NPTS / TN), NTHR, smem>>>(v_in, s_in, sv_b, vs_b, ss_b, out, B);
}

// round 9
// speedup vs baseline: 1.4012x; 1.1692x over previous
#include <cuda_runtime.h>
#include <math.h>
#include <stdint.h>

#define CC   128
#define NPTS 4096
#define TN   64
#define NG   16
#define OPT  8
#define OP2  4
#define NSL  2
#define NTHR 512
#define EPSV 1e-12f

typedef unsigned long long ull;

// Pre-expanded (se3) + transposed weights: Wt[c][o] = W[o][c]
__device__ float g_W1t [CC * CC];
__device__ float g_W2t [CC * CC];
__device__ float g_W3t [2 * CC * CC];
__device__ float g_svWt[CC * CC];
__device__ float g_vsdWt[CC * CC];
__device__ float g_vsWt[CC * CC];
__device__ float g_ssWt[CC * CC];

__global__ void prep_kernel(const float* __restrict__ weight,
                            const float* __restrict__ sv_W,
                            const float* __restrict__ cross_weight,
                            const float* __restrict__ crossfc_weight,
                            const float* __restrict__ vsdir_weight,
                            const float* __restrict__ vs_W,
                            const float* __restrict__ ss_W)
{
    const int o = blockIdx.x;
    const int t = threadIdx.x;
    __shared__ float sred[128];

    float w = (t < CC - 1) ? weight[o * (CC - 1) + t] : 0.f;
    sred[t] = w; __syncthreads();
    for (int k = 64; k > 0; k >>= 1) { if (t < k) sred[t] += sred[t + k]; __syncthreads(); }
    float rs1 = sred[0]; __syncthreads();
    if (t < CC - 1) g_W1t[t * CC + o] = w;
    else            g_W1t[(CC - 1) * CC + o] = 1.f - rs1;

    float w2 = (t < CC - 1) ? cross_weight[o * (CC - 1) + t] : 0.f;
    sred[t] = w2; __syncthreads();
    for (int k = 64; k > 0; k >>= 1) { if (t < k) sred[t] += sred[t + k]; __syncthreads(); }
    float rs2 = sred[0]; __syncthreads();
    if (t < CC - 1) g_W2t[t * CC + o] = w2;
    else            g_W2t[(CC - 1) * CC + o] = 1.f - rs2;

    float a0 = crossfc_weight[o * (2 * CC - 1) + t];
    float a1 = (t < CC - 1) ? crossfc_weight[o * (2 * CC - 1) + CC + t] : 0.f;
    sred[t] = a0 + a1; __syncthreads();
    for (int k = 64; k > 0; k >>= 1) { if (t < k) sred[t] += sred[t + k]; __syncthreads(); }
    float rs3 = sred[0]; __syncthreads();
    g_W3t[t * CC + o] = a0;
    if (t < CC - 1) g_W3t[(CC + t) * CC + o] = a1;
    else            g_W3t[(2 * CC - 1) * CC + o] = 1.f - rs3;

    g_svWt [t * CC + o] = sv_W        [o * CC + t];
    g_vsdWt[t * CC + o] = vsdir_weight[o * CC + t];
    g_vsWt [t * CC + o] = vs_W        [o * CC + t];
    g_ssWt [t * CC + o] = ss_W        [o * CC + t];
}

// ---- packed f32x2 helpers ----
#define FMA2(acc, w, x) \
    asm("fma.rn.f32x2 %0, %1, %2, %3;" : "=l"(acc) : "l"(w), "l"(x), "l"(acc))
#define ADD2(d, a, b) \
    asm("add.rn.f32x2 %0, %1, %2;" : "=l"(d) : "l"(a), "l"(b))
#define PACK_DUP(out, x) \
    asm("mov.b64 %0, {%1, %1};" : "=l"(out) : "r"(__float_as_uint(x)))

__device__ __forceinline__ float lo2(ull v) { return __uint_as_float((unsigned)v); }
__device__ __forceinline__ float hi2(ull v) { return __uint_as_float((unsigned)(v >> 32)); }
__device__ __forceinline__ ull pack2(float lo, float hi) {
    return (ull)__float_as_uint(lo) | ((ull)__float_as_uint(hi) << 32);
}
__device__ __forceinline__ ull lds2(const float* p) { return *(const ull*)p; }
__device__ __forceinline__ void sts2(float* p, ull v) { *(ull*)p = v; }

// Load 8 consecutive transposed-weight floats as 4 packed u64 (2x LDG.128).
__device__ __forceinline__ void load_w4x2(const float* __restrict__ base, ull* w2)
{
    const ulonglong2* p = (const ulonglong2*)base;
    ulonglong2 a = p[0], b = p[1];
    w2[0] = a.x; w2[1] = a.y; w2[2] = b.x; w2[3] = b.y;
}

// GEMM over 3-vector tile S[384][TN]; accumulate 8 out-ch x 3 comps x 2 slots.
template<bool INIT>
__device__ __forceinline__ void gemm3(const float* __restrict__ Wt,
                                      const float* __restrict__ S,
                                      int cb, int ob,
                                      ull aX[NSL][OP2], ull aY[NSL][OP2], ull aZ[NSL][OP2])
{
    if (INIT) {
        #pragma unroll
        for (int s = 0; s < NSL; s++)
            #pragma unroll
            for (int j = 0; j < OP2; j++) { aX[s][j] = 0; aY[s][j] = 0; aZ[s][j] = 0; }
    }
    #pragma unroll 2
    for (int c = 0; c < CC; c++) {
        ull xp = lds2(&S[(3 * c + 0) * TN + cb]);
        ull yp = lds2(&S[(3 * c + 1) * TN + cb]);
        ull zp = lds2(&S[(3 * c + 2) * TN + cb]);
        ull x0, x1, y0, y1, z0, z1;
        PACK_DUP(x0, lo2(xp)); PACK_DUP(x1, hi2(xp));
        PACK_DUP(y0, lo2(yp)); PACK_DUP(y1, hi2(yp));
        PACK_DUP(z0, lo2(zp)); PACK_DUP(z1, hi2(zp));
        ull w2[OP2]; load_w4x2(&Wt[c * CC + ob], w2);
        #pragma unroll
        for (int j = 0; j < OP2; j++) {
            FMA2(aX[0][j], w2[j], x0); FMA2(aX[1][j], w2[j], x1);
            FMA2(aY[0][j], w2[j], y0); FMA2(aY[1][j], w2[j], y1);
            FMA2(aZ[0][j], w2[j], z0); FMA2(aZ[1][j], w2[j], z1);
        }
    }
}

// value of channel (ob + jj) for slot s from packed accumulators
#define GETA(arr, s, jj) ((jj & 1) ? hi2(arr[s][jj >> 1]) : lo2(arr[s][jj >> 1]))

// ---------------------------------------------------------------------------
// Fused kernel: one block = one (b, 64-point) tile. 512 threads, 1 block/SM.
// Each thread: 8 output channels (og 0..15) x 2 adjacent points (cb, cb+1).
// ---------------------------------------------------------------------------
__global__ void __launch_bounds__(NTHR, 1)
fused_kernel(const float* __restrict__ v_in, const float* __restrict__ s_in,
             const float* __restrict__ sv_b, const float* __restrict__ vs_b,
             const float* __restrict__ ss_b, float* __restrict__ out, int B)
{
    extern __shared__ float sm[];
    float* A   = sm;                     // [384][64]  x_c, later v_cross
    float* Bm  = sm + 3 * CC * TN;       // [384][64]  s+p, later v1
    float* red = sm + 6 * CC * TN;       // [96][64]

    const int tid = threadIdx.x;
    const int nl  = tid & 31;
    const int og  = tid >> 5;            // 0..15
    const int ob  = og * OPT;
    const int cb  = nl * 2;              // column base (2 adjacent points)

    const int b  = blockIdx.x >> 6;      // 64 tiles per batch
    const int n0 = (blockIdx.x & 63) * TN;

    // ---- load x -> A, s -> Bm[0:128] (coalesced over 64 cols) ----
    {
        const int colg = tid & 63;
        const int rq   = tid >> 6;       // 0..7
        const float* src = v_in + ((size_t)b * (3 * CC)) * NPTS + n0 + colg;
        #pragma unroll 4
        for (int it = 0; it < 48; it++) {
            int r = rq + it * 8;
            A[r * TN + colg] = src[(size_t)r * NPTS];
        }
        const float* ssrc = s_in + ((size_t)b * CC) * NPTS + n0 + colg;
        #pragma unroll 4
        for (int it = 0; it < 16; it++) {
            int r = rq + it * 8;
            Bm[r * TN + colg] = ssrc[(size_t)r * NPTS];
        }
    }
    __syncthreads();

    // ---- x channel mean; center A in place ----
    float mx[NSL], my[NSL], mz[NSL];
    {
        ull px2 = 0, py2 = 0, pz2 = 0;
        #pragma unroll
        for (int j = 0; j < OPT; j++) {
            int c = ob + j;
            ADD2(px2, px2, lds2(&A[(3 * c + 0) * TN + cb]));
            ADD2(py2, py2, lds2(&A[(3 * c + 1) * TN + cb]));
            ADD2(pz2, pz2, lds2(&A[(3 * c + 2) * TN + cb]));
        }
        sts2(&red[(og * 6 + 0) * TN + cb], px2);
        sts2(&red[(og * 6 + 1) * TN + cb], py2);
        sts2(&red[(og * 6 + 2) * TN + cb], pz2);
    }
    __syncthreads();
    ull mx2 = 0, my2 = 0, mz2 = 0;
    #pragma unroll
    for (int g = 0; g < NG; g++) {
        ADD2(mx2, mx2, lds2(&red[(g * 6 + 0) * TN + cb]));
        ADD2(my2, my2, lds2(&red[(g * 6 + 1) * TN + cb]));
        ADD2(mz2, mz2, lds2(&red[(g * 6 + 2) * TN + cb]));
    }
    __syncthreads();
    #pragma unroll
    for (int s = 0; s < NSL; s++) {
        mx[s] = (s ? hi2(mx2) : lo2(mx2)) * (1.f / CC);
        my[s] = (s ? hi2(my2) : lo2(my2)) * (1.f / CC);
        mz[s] = (s ? hi2(mz2) : lo2(mz2)) * (1.f / CC);
    }
    {
        ull nmx = pack2(-mx[0], -mx[1]), nmy = pack2(-my[0], -my[1]), nmz = pack2(-mz[0], -mz[1]);
        #pragma unroll
        for (int j = 0; j < OPT; j++) {
            int c = ob + j;
            ull v;
            v = lds2(&A[(3 * c + 0) * TN + cb]); ADD2(v, v, nmx); sts2(&A[(3 * c + 0) * TN + cb], v);
            v = lds2(&A[(3 * c + 1) * TN + cb]); ADD2(v, v, nmy); sts2(&A[(3 * c + 1) * TN + cb], v);
            v = lds2(&A[(3 * c + 2) * TN + cb]); ADD2(v, v, nmz); sts2(&A[(3 * c + 2) * TN + cb], v);
        }
    }
    __syncthreads();

    ull aX[NSL][OP2], aY[NSL][OP2], aZ[NSL][OP2];

    // ================= scalar branch =================
    // dd = vsdir_weight @ x_c
    gemm3<true>(g_vsdWt, A, cb, ob, aX, aY, aZ);
    float tvv[NSL][OPT];
    {
        float pq[NSL] = {0.f, 0.f};
        #pragma unroll
        for (int jj = 0; jj < OPT; jj++) {
            int o = ob + jj;
            ull xp = lds2(&A[(3 * o + 0) * TN + cb]);
            ull yp = lds2(&A[(3 * o + 1) * TN + cb]);
            ull zp = lds2(&A[(3 * o + 2) * TN + cb]);
            #pragma unroll
            for (int s = 0; s < NSL; s++) {
                float ux = GETA(aX, s, jj), uy = GETA(aY, s, jj), uz = GETA(aZ, s, jj);
                float n2 = ux * ux + uy * uy + uz * uz;
                float inv = 1.f / fmaxf(sqrtf(n2), EPSV);
                float vx = s ? hi2(xp) : lo2(xp);
                float vy = s ? hi2(yp) : lo2(yp);
                float vz = s ? hi2(zp) : lo2(zp);
                float q = (vx * ux + vy * uy + vz * uz) * inv;
                tvv[s][jj] = q;
                pq[s] += q * q;
            }
        }
        sts2(&red[og * TN + cb], pack2(pq[0], pq[1]));
    }
    __syncthreads();
    ull Q2 = 0;
    #pragma unroll
    for (int g = 0; g < NG; g++) ADD2(Q2, Q2, lds2(&red[g * TN + cb]));
    __syncthreads();
    {
        float qinv[NSL];
        qinv[0] = 1.f / fmaxf(sqrtf(lo2(Q2)), EPSV);
        qinv[1] = 1.f / fmaxf(sqrtf(hi2(Q2)), EPSV);
        #pragma unroll
        for (int jj = 0; jj < OPT; jj++)
            sts2(&Bm[(CC + ob + jj) * TN + cb], pack2(tvv[0][jj] * qinv[0], tvv[1][jj] * qinv[1]));
    }
    __syncthreads();

    // s_out = vs_W @ p + vs_b + ss_W @ s + ss_b
    {
        ull so2[NSL][OP2];
        #pragma unroll
        for (int j = 0; j < OP2; j++) {
            ull bj = pack2(vs_b[ob + 2 * j] + ss_b[ob + 2 * j],
                           vs_b[ob + 2 * j + 1] + ss_b[ob + 2 * j + 1]);
            so2[0][j] = bj; so2[1][j] = bj;
        }
        #pragma unroll 2
        for (int c = 0; c < CC; c++) {
            ull pp = lds2(&Bm[(CC + c) * TN + cb]);
            ull sp = lds2(&Bm[c * TN + cb]);
            ull p0, p1, s0, s1;
            PACK_DUP(p0, lo2(pp)); PACK_DUP(p1, hi2(pp));
            PACK_DUP(s0, lo2(sp)); PACK_DUP(s1, hi2(sp));
            ull wva[OP2], wvb[OP2];
            load_w4x2(&g_vsWt[c * CC + ob], wva);
            load_w4x2(&g_ssWt[c * CC + ob], wvb);
            #pragma unroll
            for (int j = 0; j < OP2; j++) {
                FMA2(so2[0][j], wva[j], p0); FMA2(so2[1][j], wva[j], p1);
                FMA2(so2[0][j], wvb[j], s0); FMA2(so2[1][j], wvb[j], s1);
            }
        }
        float* outs = out + (size_t)B * CC * 3 * NPTS + ((size_t)b * CC) * NPTS + n0 + cb;
        #pragma unroll
        for (int j = 0; j < OP2; j++) {
            *(ull*)&outs[(size_t)(ob + 2 * j) * NPTS]     = pack2(lo2(so2[0][j]), lo2(so2[1][j]));
            *(ull*)&outs[(size_t)(ob + 2 * j + 1) * NPTS] = pack2(hi2(so2[0][j]), hi2(so2[1][j]));
        }
    }

    // ---- t = sv_W @ s + sv_b ----
    ull t2[NSL][OP2];
    {
        #pragma unroll
        for (int j = 0; j < OP2; j++) {
            ull bj = pack2(sv_b[ob + 2 * j], sv_b[ob + 2 * j + 1]);
            t2[0][j] = bj; t2[1][j] = bj;
        }
        #pragma unroll 2
        for (int c = 0; c < CC; c++) {
            ull sp = lds2(&Bm[c * TN + cb]);
            ull s0, s1;
            PACK_DUP(s0, lo2(sp)); PACK_DUP(s1, hi2(sp));
            ull w2[OP2]; load_w4x2(&g_svWt[c * CC + ob], w2);
            #pragma unroll
            for (int j = 0; j < OP2; j++) {
                FMA2(t2[0][j], w2[j], s0); FMA2(t2[1][j], w2[j], s1);
            }
        }
    }

    // ================= vector branch =================
    // ---- u_c = W1 @ x_c ----
    gemm3<true>(g_W1t, A, cb, ob, aX, aY, aZ);
    {
        float pu[NSL][4];
        #pragma unroll
        for (int s = 0; s < NSL; s++) {
            ull sx = 0, sy = 0, sz = 0, st = 0;
            #pragma unroll
            for (int j = 0; j < OP2; j++) {
                ADD2(sx, sx, aX[s][j]); ADD2(sy, sy, aY[s][j]); ADD2(sz, sz, aZ[s][j]);
                FMA2(st, t2[s][j], t2[s][j]);
            }
            pu[s][0] = lo2(sx) + hi2(sx); pu[s][1] = lo2(sy) + hi2(sy);
            pu[s][2] = lo2(sz) + hi2(sz); pu[s][3] = lo2(st) + hi2(st);
        }
        sts2(&red[(og * 6 + 0) * TN + cb], pack2(pu[0][0], pu[1][0]));
        sts2(&red[(og * 6 + 1) * TN + cb], pack2(pu[0][1], pu[1][1]));
        sts2(&red[(og * 6 + 2) * TN + cb], pack2(pu[0][2], pu[1][2]));
        sts2(&red[(og * 6 + 3) * TN + cb], pack2(pu[0][3], pu[1][3]));
    }
    __syncthreads();
    float mux[NSL], muy[NSL], muz[NSL], tinv[NSL];
    {
        ull sx = 0, sy = 0, sz = 0, st = 0;
        #pragma unroll
        for (int g = 0; g < NG; g++) {
            ADD2(sx, sx, lds2(&red[(g * 6 + 0) * TN + cb]));
            ADD2(sy, sy, lds2(&red[(g * 6 + 1) * TN + cb]));
            ADD2(sz, sz, lds2(&red[(g * 6 + 2) * TN + cb]));
            ADD2(st, st, lds2(&red[(g * 6 + 3) * TN + cb]));
        }
        #pragma unroll
        for (int s = 0; s < NSL; s++) {
            mux[s] = (s ? hi2(sx) : lo2(sx)) * (1.f / CC);
            muy[s] = (s ? hi2(sy) : lo2(sy)) * (1.f / CC);
            muz[s] = (s ? hi2(sz) : lo2(sz)) * (1.f / CC);
            tinv[s] = 1.f / fmaxf(sqrtf(s ? hi2(st) : lo2(st)), EPSV);
        }
    }
    __syncthreads();

    // v1 = (u_c - mu)*s2v + (mu + m) -> Bm; partial v1-mean
    float p1x[NSL] = {0.f, 0.f}, p1y[NSL] = {0.f, 0.f}, p1z[NSL] = {0.f, 0.f};
    #pragma unroll
    for (int jj = 0; jj < OPT; jj++) {
        int o = ob + jj;
        float av[NSL][3];
        #pragma unroll
        for (int s = 0; s < NSL; s++) {
            float s2v = ((jj & 1) ? hi2(t2[s][jj >> 1]) : lo2(t2[s][jj >> 1])) * tinv[s];
            av[s][0] = fmaf(GETA(aX, s, jj) - mux[s], s2v, mux[s] + mx[s]);
            av[s][1] = fmaf(GETA(aY, s, jj) - muy[s], s2v, muy[s] + my[s]);
            av[s][2] = fmaf(GETA(aZ, s, jj) - muz[s], s2v, muz[s] + mz[s]);
            p1x[s] += av[s][0]; p1y[s] += av[s][1]; p1z[s] += av[s][2];
        }
        sts2(&Bm[(3 * o + 0) * TN + cb], pack2(av[0][0], av[1][0]));
        sts2(&Bm[(3 * o + 1) * TN + cb], pack2(av[0][1], av[1][1]));
        sts2(&Bm[(3 * o + 2) * TN + cb], pack2(av[0][2], av[1][2]));
    }

    // ---- d_c = W2 @ x_c ----
    gemm3<true>(g_W2t, A, cb, ob, aX, aY, aZ);
    {
        float pd[NSL][3];
        #pragma unroll
        for (int s = 0; s < NSL; s++) {
            ull sx = 0, sy = 0, sz = 0;
            #pragma unroll
            for (int j = 0; j < OP2; j++) {
                ADD2(sx, sx, aX[s][j]); ADD2(sy, sy, aY[s][j]); ADD2(sz, sz, aZ[s][j]);
            }
            pd[s][0] = lo2(sx) + hi2(sx); pd[s][1] = lo2(sy) + hi2(sy); pd[s][2] = lo2(sz) + hi2(sz);
        }
        sts2(&red[(og * 6 + 0) * TN + cb], pack2(pd[0][0], pd[1][0]));
        sts2(&red[(og * 6 + 1) * TN + cb], pack2(pd[0][1], pd[1][1]));
        sts2(&red[(og * 6 + 2) * TN + cb], pack2(pd[0][2], pd[1][2]));
        sts2(&red[(og * 6 + 3) * TN + cb], pack2(p1x[0], p1x[1]));
        sts2(&red[(og * 6 + 4) * TN + cb], pack2(p1y[0], p1y[1]));
        sts2(&red[(og * 6 + 5) * TN + cb], pack2(p1z[0], p1z[1]));
    }
    __syncthreads();
    float dmx[NSL], dmy[NSL], dmz[NSL], m1x[NSL], m1y[NSL], m1z[NSL];
    {
        ull sx = 0, sy = 0, sz = 0, s1x = 0, s1y = 0, s1z = 0;
        #pragma unroll
        for (int g = 0; g < NG; g++) {
            ADD2(sx,  sx,  lds2(&red[(g * 6 + 0) * TN + cb]));
            ADD2(sy,  sy,  lds2(&red[(g * 6 + 1) * TN + cb]));
            ADD2(sz,  sz,  lds2(&red[(g * 6 + 2) * TN + cb]));
            ADD2(s1x, s1x, lds2(&red[(g * 6 + 3) * TN + cb]));
            ADD2(s1y, s1y, lds2(&red[(g * 6 + 4) * TN + cb]));
            ADD2(s1z, s1z, lds2(&red[(g * 6 + 5) * TN + cb]));
        }
        #pragma unroll
        for (int s = 0; s < NSL; s++) {
            dmx[s] = (s ? hi2(sx)  : lo2(sx))  * (1.f / CC);
            dmy[s] = (s ? hi2(sy)  : lo2(sy))  * (1.f / CC);
            dmz[s] = (s ? hi2(sz)  : lo2(sz))  * (1.f / CC);
            m1x[s] = (s ? hi2(s1x) : lo2(s1x)) * (1.f / CC);
            m1y[s] = (s ? hi2(s1y) : lo2(s1y)) * (1.f / CC);
            m1z[s] = (s ? hi2(s1z) : lo2(s1z)) * (1.f / CC);
        }
    }
    __syncthreads();

    // ---- center d; per-channel n2; sumsq over channels ----
    ull nn2[NSL][OP2];
    {
        float pl[NSL];
        #pragma unroll
        for (int s = 0; s < NSL; s++) {
            ull ndx, ndy, ndz;
            PACK_DUP(ndx, -dmx[s]); PACK_DUP(ndy, -dmy[s]); PACK_DUP(ndz, -dmz[s]);
            ull plsum = 0;
            #pragma unroll
            for (int j = 0; j < OP2; j++) {
                ADD2(aX[s][j], aX[s][j], ndx);
                ADD2(aY[s][j], aY[s][j], ndy);
                ADD2(aZ[s][j], aZ[s][j], ndz);
                ull n2 = 0;
                FMA2(n2, aX[s][j], aX[s][j]);
                FMA2(n2, aY[s][j], aY[s][j]);
                FMA2(n2, aZ[s][j], aZ[s][j]);
                nn2[s][j] = n2;
                ADD2(plsum, plsum, n2);
            }
            pl[s] = lo2(plsum) + hi2(plsum);
        }
        sts2(&red[og * TN + cb], pack2(pl[0], pl[1]));
    }
    __syncthreads();
    float linv[NSL];
    {
        ull L2 = 0;
        #pragma unroll
        for (int g = 0; g < NG; g++) ADD2(L2, L2, lds2(&red[g * TN + cb]));
        linv[0] = 1.f / fmaxf(sqrtf(lo2(L2)), EPSV);
        linv[1] = 1.f / fmaxf(sqrtf(hi2(L2)), EPSV);
    }
    __syncthreads();

    // ---- v_cross = cross(ceq, v1 - v1m) + v1 -> A ----
    #pragma unroll
    for (int jj = 0; jj < OPT; jj++) {
        int o = ob + jj;
        ull v1xp = lds2(&Bm[(3 * o + 0) * TN + cb]);
        ull v1yp = lds2(&Bm[(3 * o + 1) * TN + cb]);
        ull v1zp = lds2(&Bm[(3 * o + 2) * TN + cb]);
        float cx[NSL], cy[NSL], cz[NSL];
        #pragma unroll
        for (int s = 0; s < NSL; s++) {
            float n2 = (jj & 1) ? hi2(nn2[s][jj >> 1]) : lo2(nn2[s][jj >> 1]);
            float nyv = sqrtf(n2);
            float cf = (nyv * linv[s]) / fmaxf(nyv, EPSV);
            float ex = GETA(aX, s, jj) * cf;
            float ey = GETA(aY, s, jj) * cf;
            float ez = GETA(aZ, s, jj) * cf;
            float ax = s ? hi2(v1xp) : lo2(v1xp);
            float ay = s ? hi2(v1yp) : lo2(v1yp);
            float az = s ? hi2(v1zp) : lo2(v1zp);
            float wx = ax - m1x[s], wy = ay - m1y[s], wz = az - m1z[s];
            cx[s] = ey * wz - ez * wy + ax;
            cy[s] = ez * wx - ex * wz + ay;
            cz[s] = ex * wy - ey * wx + az;
        }
        sts2(&A[(3 * o + 0) * TN + cb], pack2(cx[0], cx[1]));
        sts2(&A[(3 * o + 1) * TN + cb], pack2(cy[0], cy[1]));
        sts2(&A[(3 * o + 2) * TN + cb], pack2(cz[0], cz[1]));
    }
    __syncthreads();

    // ---- v_out = W3[:, :128] @ v_cross (A) + W3[:, 128:] @ v1 (Bm) ----
    gemm3<true >(g_W3t,           A,  cb, ob, aX, aY, aZ);
    gemm3<false>(g_W3t + CC * CC, Bm, cb, ob, aX, aY, aZ);
    {
        float* outv = out + ((size_t)b * CC) * 3 * NPTS + n0 + cb;
        #pragma unroll
        for (int j = 0; j < OP2; j++) {
            int o0 = ob + 2 * j, o1 = o0 + 1;
            *(ull*)&outv[(size_t)(3 * o0 + 0) * NPTS] = pack2(lo2(aX[0][j]), lo2(aX[1][j]));
            *(ull*)&outv[(size_t)(3 * o0 + 1) * NPTS] = pack2(lo2(aY[0][j]), lo2(aY[1][j]));
            *(ull*)&outv[(size_t)(3 * o0 + 2) * NPTS] = pack2(lo2(aZ[0][j]), lo2(aZ[1][j]));
            *(ull*)&outv[(size_t)(3 * o1 + 0) * NPTS] = pack2(hi2(aX[0][j]), hi2(aX[1][j]));
            *(ull*)&outv[(size_t)(3 * o1 + 1) * NPTS] = pack2(hi2(aY[0][j]), hi2(aY[1][j]));
            *(ull*)&outv[(size_t)(3 * o1 + 2) * NPTS] = pack2(hi2(aZ[0][j]), hi2(aZ[1][j]));
        }
    }
}

extern "C" void kernel_launch(void* const* d_in, const int* in_sizes, int n_in,
                              void* d_out, int out_size)
{
    const float* v_in      = (const float*)d_in[0];
    const float* s_in      = (const float*)d_in[1];
    const float* weight    = (const float*)d_in[2];
    const float* sv_W      = (const float*)d_in[3];
    const float* sv_b      = (const float*)d_in[4];
    const float* cross_w   = (const float*)d_in[5];
    const float* crossfc_w = (const float*)d_in[6];
    const float* vsdir_w   = (const float*)d_in[7];
    const float* vs_W      = (const float*)d_in[8];
    const float* vs_b      = (const float*)d_in[9];
    const float* ss_W      = (const float*)d_in[10];
    const float* ss_b      = (const float*)d_in[11];
    float* out = (float*)d_out;

    const int B = in_sizes[0] / (CC * 3 * NPTS);   // 16

    prep_kernel<<<CC, CC>>>(weight, sv_W, cross_w, crossfc_w, vsdir_w, vs_W, ss_W);

    // smem: 2 * 384*64 + 96*64 floats = 221,184 B -> 1 block/SM, 16 warps
    const size_t smem = (size_t)(6 * CC * TN + 96 * TN) * sizeof(float);
    cudaFuncSetAttribute(fused_kernel, cudaFuncAttributeMaxDynamicSharedMemorySize, (int)smem);
    fused_kernel<<<B * (NPTS / TN), NTHR, smem>>>(v_in, s_in, sv_b, vs_b, ss_b, out, B);
}